// round 17
// baseline (speedup 1.0000x reference)
#include <cuda_runtime.h>
#include <cuda_fp16.h>
#include <cstdint>

#define DEVINL __device__ __forceinline__

namespace {

constexpr int Bb = 2, Hh = 16, Ss = 2048, Dd = 128;
constexpr int TM = 128;           // query tile
constexpr int TN = 128;           // key tile
constexpr int NKT = Ss / TN;      // 16
constexpr int NTHREADS = 512;     // 16 warps: 8 row-strips x 2 t-halves
constexpr int ROWB = 272;         // 128 fp16 * 2B + 16B pad (conflict-free ldmatrix)
constexpr int TILE_B = 128 * ROWB;            // 34816
// planes: Q K0 K1 V0 V1
constexpr uint32_t SMEM_BYTES = 5 * TILE_B;   // 174080

constexpr size_t NELEM = (size_t)Bb * Hh * Ss * Dd;  // 8,388,608 per tensor

}  // namespace

// 32 MB of pre-rounded fp16 K and V (static scratch — legal)
__device__ __align__(16) __half g_K[NELEM];
__device__ __align__(16) __half g_V[NELEM];

namespace {

DEVINL uint32_t smem_u32(const void* p) {
  uint32_t a;
  asm("{ .reg .u64 t; cvta.to.shared.u64 t, %1; cvt.u32.u64 %0, t; }" : "=r"(a) : "l"(p));
  return a;
}

DEVINL uint32_t toff(int r, int c) { return (uint32_t)(r * ROWB + c * 2); }

DEVINL uint32_t pack2h(__half lo_el, __half hi_el) {
  return ((uint32_t)__half_as_ushort(hi_el) << 16) | (uint32_t)__half_as_ushort(lo_el);
}

// ---------------- cp.async helpers ----------------
DEVINL void cp16(uint32_t dst, const void* src) {
  asm volatile("cp.async.cg.shared.global [%0], [%1], 16;" :: "r"(dst), "l"(src));
}
#define CP_COMMIT()  asm volatile("cp.async.commit_group;" ::: "memory")
#define CP_WAIT3()   asm volatile("cp.async.wait_group 3;" ::: "memory")
#define CP_WAIT0()   asm volatile("cp.async.wait_group 0;" ::: "memory")

// copy one [128 x 128] fp16 tile gmem -> padded smem (4 cp.async/thread)
DEVINL void load_tile(uint32_t dst, const __half* src, int tid) {
#pragma unroll
  for (int i = 0; i < 4; ++i) {
    int c = tid + i * NTHREADS;       // chunk id: 2048 chunks of 16B
    int row = c >> 4, ch = c & 15;
    cp16(dst + (uint32_t)(row * ROWB + ch * 16), src + row * Dd + ch * 8);
  }
}

// ---------------- MMA / ldmatrix wrappers ----------------
DEVINL void ldsm4(uint32_t* r, uint32_t addr) {
  asm volatile("ldmatrix.sync.aligned.m8n8.x4.shared.b16 {%0,%1,%2,%3}, [%4];"
               : "=r"(r[0]), "=r"(r[1]), "=r"(r[2]), "=r"(r[3]) : "r"(addr));
}
DEVINL void ldsm4t(uint32_t* r, uint32_t addr) {
  asm volatile("ldmatrix.sync.aligned.m8n8.x4.trans.shared.b16 {%0,%1,%2,%3}, [%4];"
               : "=r"(r[0]), "=r"(r[1]), "=r"(r[2]), "=r"(r[3]) : "r"(addr));
}
// fp16 inputs, fp32 accum; non-volatile so ptxas can schedule.
DEVINL void mma16816(float* c, const uint32_t* a, uint32_t b0, uint32_t b1) {
  asm("mma.sync.aligned.m16n8k16.row.col.f32.f16.f16.f32 "
      "{%0,%1,%2,%3}, {%4,%5,%6,%7}, {%8,%9}, {%0,%1,%2,%3};"
      : "+f"(c[0]), "+f"(c[1]), "+f"(c[2]), "+f"(c[3])
      : "r"(a[0]), "r"(a[1]), "r"(a[2]), "r"(a[3]), "r"(b0), "r"(b1));
}

// ---------------- pre-pass: fp32 K,V -> fp16 (rounded once) ----------------
__global__ void __launch_bounds__(256)
conv_kernel(const float* __restrict__ k, const float* __restrict__ v) {
  size_t i = (size_t)blockIdx.x * 256 + threadIdx.x;  // float4 index
  float4 a = ((const float4*)k)[i];
  float4 b = ((const float4*)v)[i];
  ((uint2*)g_K)[i] = make_uint2(
      pack2h(__float2half_rn(a.x), __float2half_rn(a.y)),
      pack2h(__float2half_rn(a.z), __float2half_rn(a.w)));
  ((uint2*)g_V)[i] = make_uint2(
      pack2h(__float2half_rn(b.x), __float2half_rn(b.y)),
      pack2h(__float2half_rn(b.z), __float2half_rn(b.w)));
}

__global__ void __launch_bounds__(NTHREADS, 1)
attn_mask_kernel(const float* __restrict__ q, const float* __restrict__ mask,
                 float* __restrict__ out) {
  extern __shared__ char smem[];
  const uint32_t sb = smem_u32(smem);
  const int tid = threadIdx.x, wid = tid >> 5, lane = tid & 31;
  const int bh = (int)blockIdx.z * Hh + (int)blockIdx.y;
  const int s0 = (int)blockIdx.x * TM;

  char* QF = smem;  // single fp16 Q plane
  // K buffers at planes 1,2; V buffers at planes 3,4

  const __half* kg = g_K + (size_t)bh * Ss * Dd;
  const __half* vg = g_V + (size_t)bh * Ss * Dd;

  // ---- prologue: async-load K(0),V(0),K(1),V(1) (4 groups) ----
  load_tile(sb + 1 * TILE_B, kg, tid);                    CP_COMMIT();
  load_tile(sb + 3 * TILE_B, vg, tid);                    CP_COMMIT();
  load_tile(sb + 2 * TILE_B, kg + (size_t)TN * Dd, tid);  CP_COMMIT();
  load_tile(sb + 4 * TILE_B, vg + (size_t)TN * Dd, tid);  CP_COMMIT();

  // ---- load + round Q tile to fp16 (overlaps the async copies) ----
  {
    const float4* qsrc = (const float4*)(q + ((size_t)bh * Ss + s0) * Dd);
#pragma unroll
    for (int i = 0; i < 8; ++i) {
      int f = tid + i * NTHREADS;
      float4 val = qsrc[f];
      int e = f * 4;
      uint32_t off = toff(e >> 7, e & 127);
      *reinterpret_cast<uint2*>(QF + off) = make_uint2(
          pack2h(__float2half_rn(val.x), __float2half_rn(val.y)),
          pack2h(__float2half_rn(val.z), __float2half_rn(val.w)));
    }
  }

  // warp tiling: wi = 16-row strip (8 strips), wj = t-half (64 cols)
  const int wi = wid >> 1;
  const int wj = wid & 1;
  const int wrow0 = wi * 16;
  const int tcol0 = wj * 64;

  // accumulators: S [8 n-frags][4] (t-half), O [16 n-frags][4] partial over t-half
  float S[8][4];
  float O[16][4];
#pragma unroll
  for (int i = 0; i < 16; ++i) { O[i][0] = O[i][1] = O[i][2] = O[i][3] = 0.f; }

  const int lrow = lane & 7;
  const int lq = (lane >> 3) & 1;
  const int lh = lane >> 4;

  // ldmatrix lane base addresses
  const uint32_t qA = sb + toff(wrow0 + lrow + lq * 8, lh * 8);
  // K B-frags: t-rows from this warp's t-half
  const uint32_t kB[2] = {sb + 1 * TILE_B + toff(tcol0 + lrow + lh * 8, lq * 8),
                          sb + 2 * TILE_B + toff(tcol0 + lrow + lh * 8, lq * 8)};
  // V B-frags (trans): t-rows from this warp's t-half, all 128 d-cols
  const uint32_t vB[2] = {sb + 3 * TILE_B + toff(tcol0 + lrow + lq * 8, lh * 8),
                          sb + 4 * TILE_B + toff(tcol0 + lrow + lq * 8, lh * 8)};

  const int mr = wrow0 + (lane >> 2);      // this thread's row (and +8)
  const int mc = (lane & 3) * 2;
  const float* mbase = mask + ((size_t)bh * Ss + (s0 + mr)) * Ss + tcol0;

#pragma unroll 1
  for (int kt = 0; kt < NKT; ++kt) {
    const int t0 = kt * TN;
    const int buf = kt & 1;
    const int t2 = (kt + 2 < NKT) ? (kt + 2) : 0;  // clamp (harmless reload)

    // ---- K(kt) ready: at most 3 newer groups outstanding ----
    CP_WAIT3();
    __syncthreads();

    // ---- GEMM1: S[16 x 64] = Q @ K[t-half]^T (fp16 single-term) ----
#pragma unroll
    for (int i = 0; i < 8; ++i) { S[i][0] = S[i][1] = S[i][2] = S[i][3] = 0.f; }
#pragma unroll
    for (int kk = 0; kk < 8; ++kk) {
      uint32_t a_[4];
      ldsm4(a_, qA + kk * 32);
#pragma unroll
      for (int ntp = 0; ntp < 4; ++ntp) {
        uint32_t b_[4];
        ldsm4(b_, kB[buf] + (uint32_t)(ntp * 16 * ROWB) + kk * 32);
        mma16816(S[2 * ntp],     a_, b_[0], b_[1]);
        mma16816(S[2 * ntp + 1], a_, b_[2], b_[3]);
      }
    }

    __syncthreads();  // all warps done reading K buf

    // ---- issue K(kt+2) into this K buffer (overlaps GEMM2) ----
    load_tile(kB[buf] - toff(tcol0 + lrow + lh * 8, lq * 8),
              kg + (size_t)t2 * TN * Dd, tid);
    CP_COMMIT();
    CP_WAIT3();       // V(kt) complete
    __syncthreads();

    // ---- GEMM2: O(partial) += (S*mask) @ V[t-half, :] (fp16 single-term P) ----
#pragma unroll
    for (int kk = 0; kk < 4; ++kk) {
      // mask n-frags 2kk, 2kk+1 of this warp's t-half (streamed)
      {
        const float* mp0 = mbase + t0 + (2 * kk) * 8 + mc;
        const float* mp1 = mbase + t0 + (2 * kk + 1) * 8 + mc;
        float2 m0 = __ldcs((const float2*)mp0);
        float2 m1 = __ldcs((const float2*)(mp0 + 8 * Ss));
        float2 m2 = __ldcs((const float2*)mp1);
        float2 m3 = __ldcs((const float2*)(mp1 + 8 * Ss));
        S[2 * kk][0] *= m0.x;     S[2 * kk][1] *= m0.y;
        S[2 * kk][2] *= m1.x;     S[2 * kk][3] *= m1.y;
        S[2 * kk + 1][0] *= m2.x; S[2 * kk + 1][1] *= m2.y;
        S[2 * kk + 1][2] *= m3.x; S[2 * kk + 1][3] *= m3.y;
      }
      // build P A-fragment (rounded fp16); k = tcol0 + kk*16 matches S cols
      uint32_t ph[4];
      ph[0] = pack2h(__float2half_rn(S[2 * kk][0]), __float2half_rn(S[2 * kk][1]));
      ph[1] = pack2h(__float2half_rn(S[2 * kk][2]), __float2half_rn(S[2 * kk][3]));
      ph[2] = pack2h(__float2half_rn(S[2 * kk + 1][0]), __float2half_rn(S[2 * kk + 1][1]));
      ph[3] = pack2h(__float2half_rn(S[2 * kk + 1][2]), __float2half_rn(S[2 * kk + 1][3]));
#pragma unroll
      for (int np = 0; np < 8; ++np) {
        uint32_t b_[4];
        ldsm4t(b_, vB[buf] + (uint32_t)(kk * 16 * ROWB) + np * 32);
        mma16816(O[2 * np],     ph, b_[0], b_[1]);
        mma16816(O[2 * np + 1], ph, b_[2], b_[3]);
      }
    }

    __syncthreads();  // all warps done reading V buf

    // ---- issue V(kt+2) into this V buffer (overlaps next GEMM1) ----
    load_tile(vB[buf] - toff(tcol0 + lrow + lq * 8, lh * 8),
              vg + (size_t)t2 * TN * Dd, tid);
    CP_COMMIT();
  }

  // ---- quiesce all outstanding cp.async before repurposing smem ----
  CP_WAIT0();
  __syncthreads();

  // ---- epilogue: combine t-half partial O via smem, then -> gmem ----
  {
    float* SP = (float*)(smem + 1 * TILE_B);   // K/V buffers dead; 128 x 132 floats
    if (wj == 1) {
#pragma unroll
      for (int nf = 0; nf < 16; ++nf) {
        SP[mr * 132 + nf * 8 + mc]           = O[nf][0];
        SP[mr * 132 + nf * 8 + mc + 1]       = O[nf][1];
        SP[(mr + 8) * 132 + nf * 8 + mc]     = O[nf][2];
        SP[(mr + 8) * 132 + nf * 8 + mc + 1] = O[nf][3];
      }
    }
    __syncthreads();
    if (wj == 0) {
      float* ob = out + ((size_t)bh * Ss + (s0 + mr)) * Dd + mc;
#pragma unroll
      for (int nf = 0; nf < 16; ++nf) {
        float2 v0 = make_float2(O[nf][0] + SP[mr * 132 + nf * 8 + mc],
                                O[nf][1] + SP[mr * 132 + nf * 8 + mc + 1]);
        float2 v1 = make_float2(O[nf][2] + SP[(mr + 8) * 132 + nf * 8 + mc],
                                O[nf][3] + SP[(mr + 8) * 132 + nf * 8 + mc + 1]);
        *(float2*)(ob + nf * 8) = v0;
        *(float2*)(ob + 8 * Dd + nf * 8) = v1;
      }
    }
  }
}

}  // namespace

extern "C" void kernel_launch(void* const* d_in, const int* in_sizes, int n_in,
                              void* d_out, int out_size) {
  (void)in_sizes; (void)n_in; (void)out_size;
  const float* q = (const float*)d_in[0];
  const float* k = (const float*)d_in[1];
  const float* v = (const float*)d_in[2];
  const float* m = (const float*)d_in[3];
  float* out = (float*)d_out;

  // pre-pass: round K, V to fp16 (NELEM/4 float4s, 256 thr/blk)
  conv_kernel<<<(int)(NELEM / 4 / 256), 256>>>(k, v);

  cudaFuncSetAttribute(attn_mask_kernel, cudaFuncAttributeMaxDynamicSharedMemorySize,
                       SMEM_BYTES);
  dim3 grid(Ss / TM, Hh, Bb);
  attn_mask_kernel<<<grid, NTHREADS, SMEM_BYTES>>>(q, m, out);
}